// round 13
// baseline (speedup 1.0000x reference)
#include <cuda_runtime.h>
#include <cuda_bf16.h>
#include <cstdint>

#define N_NODES 100000
#define N_EDGES 1600000
#define IN_DIM  256
#define OUT_DIM 64

#define SCAN_BLK    98
#define SCAN_CHUNK  1024
#define E4          (N_EDGES / 4)
#define E8          (N_EDGES / 8)
#define TC_BLOCKS   ((N_NODES + 63) / 64)    // 1563 (64 rows per CTA)

// Scratch (device globals; g_cnt starts zeroed and is self-reset each run).
__device__ float               g_X[(size_t)N_NODES * OUT_DIM];
__device__ int                 g_cnt[N_NODES];
__device__ int                 g_offs[N_NODES + 1];
__device__ int                 g_cursor[N_NODES];
__device__ int                 g_sorted_cols[N_EDGES];
__device__ unsigned long long  g_state[SCAN_BLK];
// Precomputed B fragments (canonical mma.sync layout, VERIFIED):
// index = ((s*8 + t)*32 + lane), s = kstep (16), t = ntile (8).
__device__ uint2               g_Bfh[4096];
__device__ uint2               g_Bfl[4096];

// ===========================================================================
// Launch 1: histogram + zero lookback state + precompute B fragments.
// ===========================================================================
__global__ __launch_bounds__(256) void hist_kernel(
    const int4* __restrict__ rows4, const float* __restrict__ w)
{
    if (blockIdx.x == 0 && threadIdx.x < SCAN_BLK)
        g_state[threadIdx.x] = 0ULL;

    if (blockIdx.x < 16) {
        const int idx = blockIdx.x * 256 + threadIdx.x;  // (s*8+t)*32 + lane
        const int lane = idx & 31;
        const int st   = idx >> 5;
        const int s    = st >> 3;
        const int t    = st & 7;
        const int n    = t * 8 + (lane >> 2);
        const int k0   = s * 16 + (lane & 3) * 2;

        const float v00 = __ldg(&w[(size_t)k0 * OUT_DIM + n]);
        const float v01 = __ldg(&w[(size_t)(k0 + 1) * OUT_DIM + n]);
        const float v10 = __ldg(&w[(size_t)(k0 + 8) * OUT_DIM + n]);
        const float v11 = __ldg(&w[(size_t)(k0 + 9) * OUT_DIM + n]);

        __nv_bfloat16 h00 = __float2bfloat16(v00);
        __nv_bfloat16 h01 = __float2bfloat16(v01);
        __nv_bfloat16 h10 = __float2bfloat16(v10);
        __nv_bfloat16 h11 = __float2bfloat16(v11);
        __nv_bfloat16 l00 = __float2bfloat16(v00 - __bfloat162float(h00));
        __nv_bfloat16 l01 = __float2bfloat16(v01 - __bfloat162float(h01));
        __nv_bfloat16 l10 = __float2bfloat16(v10 - __bfloat162float(h10));
        __nv_bfloat16 l11 = __float2bfloat16(v11 - __bfloat162float(h11));

        uint2 bh, bl;
        bh.x = (uint32_t)__bfloat16_as_ushort(h00) |
               ((uint32_t)__bfloat16_as_ushort(h01) << 16);
        bh.y = (uint32_t)__bfloat16_as_ushort(h10) |
               ((uint32_t)__bfloat16_as_ushort(h11) << 16);
        bl.x = (uint32_t)__bfloat16_as_ushort(l00) |
               ((uint32_t)__bfloat16_as_ushort(l01) << 16);
        bl.y = (uint32_t)__bfloat16_as_ushort(l10) |
               ((uint32_t)__bfloat16_as_ushort(l11) << 16);
        g_Bfh[idx] = bh;
        g_Bfl[idx] = bl;
    }

    const int i = blockIdx.x * blockDim.x + threadIdx.x;
    if (i < E4) {
        const int4 r = __ldg(&rows4[i]);
        atomicAdd(&g_cnt[r.x], 1);
        atomicAdd(&g_cnt[r.y], 1);
        atomicAdd(&g_cnt[r.z], 1);
        atomicAdd(&g_cnt[r.w], 1);
    }
}

// ===========================================================================
// Launch 2: decoupled-lookback exclusive scan
// ===========================================================================
__global__ __launch_bounds__(256) void scan_kernel()
{
    __shared__ int part[256];
    __shared__ int sbase;
    const int t = threadIdx.x;
    const int b = blockIdx.x;
    const int i0 = b * SCAN_CHUNK + t * 4;

    int c[4];
    int s = 0;
    #pragma unroll
    for (int j = 0; j < 4; j++) {
        c[j] = (i0 + j < N_NODES) ? g_cnt[i0 + j] : 0;
        s += c[j];
    }
    part[t] = s;
    __syncthreads();
    #pragma unroll
    for (int d = 1; d < 256; d <<= 1) {
        int u = (t >= d) ? part[t - d] : 0;
        __syncthreads();
        part[t] += u;
        __syncthreads();
    }
    const int total = part[255];

    if (t == 0) {
        unsigned long long packed =
            ((unsigned long long)total << 2) | (b == 0 ? 2ULL : 1ULL);
        atomicExch(&g_state[b], packed);
        if (b == 0) sbase = 0;
    }
    if (b > 0 && t < 32) {
        int base = 0;
        int p = b - 1;
        while (true) {
            const int i = p - t;
            unsigned long long st;
            if (i >= 0) {
                do { st = atomicAdd(&g_state[i], 0ULL); } while ((st & 3ULL) == 0ULL);
            } else st = 2ULL;
            const int flag = (int)(st & 3ULL);
            const int val  = (int)(st >> 2);
            const unsigned dm = __ballot_sync(0xFFFFFFFFu, flag == 2);
            int contrib;
            if (dm) { const int fd = __ffs(dm) - 1; contrib = (t <= fd) ? val : 0; }
            else contrib = val;
            #pragma unroll
            for (int d = 16; d > 0; d >>= 1)
                contrib += __shfl_down_sync(0xFFFFFFFFu, contrib, d);
            contrib = __shfl_sync(0xFFFFFFFFu, contrib, 0);
            base += contrib;
            if (dm) break;
            p -= 32;
        }
        if (t == 0) {
            sbase = base;
            atomicExch(&g_state[b],
                       ((unsigned long long)(base + total) << 2) | 2ULL);
        }
    }
    __syncthreads();

    int run = sbase + part[t] - s;
    #pragma unroll
    for (int j = 0; j < 4; j++) {
        if (i0 + j < N_NODES) { g_offs[i0 + j] = run; g_cursor[i0 + j] = run; }
        run += c[j];
    }
    if (b == 0 && t == 0) g_offs[N_NODES] = N_EDGES;
}

// ===========================================================================
// Launch 3: bucket fill (8 edges/thread -> MLP 8 on atomic return chain)
// ===========================================================================
__global__ __launch_bounds__(256) void fill_kernel(
    const int4* __restrict__ rows4, const int4* __restrict__ cols4)
{
    const int i = blockIdx.x * blockDim.x + threadIdx.x;
    if (i >= E8) return;
    const int4 r0 = __ldg(&rows4[2 * i]);
    const int4 r1 = __ldg(&rows4[2 * i + 1]);
    const int4 c0 = __ldg(&cols4[2 * i]);
    const int4 c1 = __ldg(&cols4[2 * i + 1]);

    const int p0 = atomicAdd(&g_cursor[r0.x], 1);
    const int p1 = atomicAdd(&g_cursor[r0.y], 1);
    const int p2 = atomicAdd(&g_cursor[r0.z], 1);
    const int p3 = atomicAdd(&g_cursor[r0.w], 1);
    const int p4 = atomicAdd(&g_cursor[r1.x], 1);
    const int p5 = atomicAdd(&g_cursor[r1.y], 1);
    const int p6 = atomicAdd(&g_cursor[r1.z], 1);
    const int p7 = atomicAdd(&g_cursor[r1.w], 1);

    g_sorted_cols[p0] = c0.x;
    g_sorted_cols[p1] = c0.y;
    g_sorted_cols[p2] = c0.z;
    g_sorted_cols[p3] = c0.w;
    g_sorted_cols[p4] = c1.x;
    g_sorted_cols[p5] = c1.y;
    g_sorted_cols[p6] = c1.z;
    g_sorted_cols[p7] = c1.w;
}

// ===========================================================================
// Launch 4 (PROFILED): mma.sync bf16-split GEMM, zero smem, 1 m-tile/warp,
// SOFTWARE-PIPELINED A loads: convert current k-step, immediately issue
// next k-step's loads (latency hidden under 16 B-loads + 24 HMMA), 5 CTAs/SM.
// D = Ah*Bh + Ah*Bl + Al*Bh, fp32 accumulation.
// ===========================================================================
__device__ __forceinline__ void cvt_split(float2 v, uint32_t& h, uint32_t& l)
{
    asm("cvt.rn.bf16x2.f32 %0, %1, %2;" : "=r"(h) : "f"(v.y), "f"(v.x));
    const float h0 = __uint_as_float(h << 16);
    const float h1 = __uint_as_float(h & 0xFFFF0000u);
    const float l0 = v.x - h0;
    const float l1 = v.y - h1;
    asm("cvt.rn.bf16x2.f32 %0, %1, %2;" : "=r"(l) : "f"(l1), "f"(l0));
}

__device__ __forceinline__ void mma_bf16(float* d, const uint32_t* a, uint2 b)
{
    asm volatile(
        "mma.sync.aligned.m16n8k16.row.col.f32.bf16.bf16.f32 "
        "{%0,%1,%2,%3}, {%4,%5,%6,%7}, {%8,%9}, {%0,%1,%2,%3};"
        : "+f"(d[0]), "+f"(d[1]), "+f"(d[2]), "+f"(d[3])
        : "r"(a[0]), "r"(a[1]), "r"(a[2]), "r"(a[3]),
          "r"(b.x), "r"(b.y));
}

__global__ __launch_bounds__(128, 5) void gemm_mma_kernel(const float* __restrict__ in)
{
    const int tid  = threadIdx.x;
    const int wid  = tid >> 5;
    const int lane = tid & 31;
    const int m0   = blockIdx.x * 64 + wid * 16;   // warp's 16-row tile

    // Lane's two A rows (clamped for safe loads; stores guarded).
    const int raw_a = m0 + (lane >> 2);
    const int raw_b = raw_a + 8;
    const int ra = raw_a < N_NODES ? raw_a : (N_NODES - 1);
    const int rb = raw_b < N_NODES ? raw_b : (N_NODES - 1);
    const int kl = (lane & 3) * 2;
    const float* p0 = in + (size_t)ra * IN_DIM + kl;
    const float* p1 = in + (size_t)rb * IN_DIM + kl;

    float d[8][4];
    #pragma unroll
    for (int t = 0; t < 8; t++)
        #pragma unroll
        for (int j = 0; j < 4; j++) d[t][j] = 0.f;

    // Prologue: preload k-step 0.
    float2 v0 = __ldg((const float2*)(p0));
    float2 v1 = __ldg((const float2*)(p1));
    float2 v2 = __ldg((const float2*)(p0 + 8));
    float2 v3 = __ldg((const float2*)(p1 + 8));

    #pragma unroll 1
    for (int s = 0; s < 16; s++) {
        // Convert current k-step (frees v registers)...
        uint32_t ah[4], al[4];
        cvt_split(v0, ah[0], al[0]);
        cvt_split(v1, ah[1], al[1]);
        cvt_split(v2, ah[2], al[2]);
        cvt_split(v3, ah[3], al[3]);

        // ...then immediately issue next k-step's loads (latency hidden
        // under the B-loads + 24 HMMA below). s=15 harmlessly reloads s=0.
        const int kn = ((s + 1) & 15) * 16;
        v0 = __ldg((const float2*)(p0 + kn));
        v1 = __ldg((const float2*)(p1 + kn));
        v2 = __ldg((const float2*)(p0 + kn + 8));
        v3 = __ldg((const float2*)(p1 + kn + 8));

        const int bi = (s * 8) * 32 + lane;
        #pragma unroll
        for (int t = 0; t < 8; t++) {
            const uint2 bh = __ldg(&g_Bfh[bi + t * 32]);
            const uint2 bl = __ldg(&g_Bfl[bi + t * 32]);
            mma_bf16(d[t], ah, bh);
            mma_bf16(d[t], ah, bl);
            mma_bf16(d[t], al, bh);
        }
    }

    // Epilogue (guarded stores).
    const int cbase = (lane & 3) * 2;
    #pragma unroll
    for (int t = 0; t < 8; t++) {
        const int c = t * 8 + cbase;
        if (raw_a < N_NODES)
            *(float2*)(g_X + (size_t)raw_a * OUT_DIM + c) =
                make_float2(d[t][0], d[t][1]);
        if (raw_b < N_NODES)
            *(float2*)(g_X + (size_t)raw_b * OUT_DIM + c) =
                make_float2(d[t][2], d[t][3]);
    }
}

// ===========================================================================
// Launch 5: CSR aggregation + fused sigmoid (resets g_cnt for next replay)
// ===========================================================================
__global__ __launch_bounds__(256) void aggregate_kernel(float* __restrict__ out)
{
    const int hw   = threadIdx.x >> 4;
    const int hl   = threadIdx.x & 15;
    const int node = blockIdx.x * 16 + hw;
    if (node >= N_NODES) return;

    const int start = g_offs[node];
    const int end   = g_offs[node + 1];
    if (hl == 0) g_cnt[node] = 0;

    const float* Xl = g_X + hl * 4;

    float4 A = make_float4(0.f, 0.f, 0.f, 0.f);
    float4 B = make_float4(0.f, 0.f, 0.f, 0.f);

    int idx = start;
    for (; idx + 8 <= end; idx += 8) {
        int c[8];
        #pragma unroll
        for (int j = 0; j < 8; j++) c[j] = __ldg(&g_sorted_cols[idx + j]);
        float4 v[8];
        #pragma unroll
        for (int j = 0; j < 8; j++)
            v[j] = __ldg((const float4*)(Xl + (size_t)c[j] * OUT_DIM));
        #pragma unroll
        for (int j = 0; j < 8; j += 2) {
            A.x += v[j].x;     A.y += v[j].y;
            A.z += v[j].z;     A.w += v[j].w;
            B.x += v[j + 1].x; B.y += v[j + 1].y;
            B.z += v[j + 1].z; B.w += v[j + 1].w;
        }
    }
    for (; idx + 2 <= end; idx += 2) {
        const int c0 = __ldg(&g_sorted_cols[idx]);
        const int c1 = __ldg(&g_sorted_cols[idx + 1]);
        const float4 v0 = __ldg((const float4*)(Xl + (size_t)c0 * OUT_DIM));
        const float4 v1 = __ldg((const float4*)(Xl + (size_t)c1 * OUT_DIM));
        A.x += v0.x; A.y += v0.y; A.z += v0.z; A.w += v0.w;
        B.x += v1.x; B.y += v1.y; B.z += v1.z; B.w += v1.w;
    }
    if (idx < end) {
        const int c = __ldg(&g_sorted_cols[idx]);
        const float4 v = __ldg((const float4*)(Xl + (size_t)c * OUT_DIM));
        A.x += v.x; A.y += v.y; A.z += v.z; A.w += v.w;
    }
    A.x += B.x; A.y += B.y; A.z += B.z; A.w += B.w;

    float4 o;
    o.x = 1.0f / (1.0f + __expf(-A.x));
    o.y = 1.0f / (1.0f + __expf(-A.y));
    o.z = 1.0f / (1.0f + __expf(-A.z));
    o.w = 1.0f / (1.0f + __expf(-A.w));
    *(float4*)(out + (size_t)node * OUT_DIM + hl * 4) = o;
}

extern "C" void kernel_launch(void* const* d_in, const int* in_sizes, int n_in,
                              void* d_out, int out_size)
{
    const float* inputs = (const float*)d_in[0];
    const int*   eidx   = (const int*)d_in[1];
    const float* weight = (const float*)d_in[2];
    float*       out    = (float*)d_out;

    const int4* erows4 = (const int4*)eidx;
    const int4* ecols4 = (const int4*)(eidx + N_EDGES);

    hist_kernel<<<(E4 + 255) / 256, 256>>>(erows4, weight);         // 1
    scan_kernel<<<SCAN_BLK, 256>>>();                               // 2
    fill_kernel<<<(E8 + 255) / 256, 256>>>(erows4, ecols4);         // 3
    gemm_mma_kernel<<<TC_BLOCKS, 128>>>(inputs);                    // 4 (profiled)
    aggregate_kernel<<<(N_NODES + 15) / 16, 256>>>(out);            // 5
}

// round 14
// speedup vs baseline: 1.0892x; 1.0892x over previous
#include <cuda_runtime.h>
#include <cuda_bf16.h>
#include <cstdint>

#define N_NODES 100000
#define N_EDGES 1600000
#define IN_DIM  256
#define OUT_DIM 64

#define SCAN_BLK    98
#define SCAN_CHUNK  1024
#define E4          (N_EDGES / 4)
#define E8          (N_EDGES / 8)
#define TC_BLOCKS   ((N_NODES + 127) / 128)   // 782 (128 rows per CTA)

// Scratch (device globals; g_cnt starts zeroed and is self-reset each run).
__device__ float               g_X[(size_t)N_NODES * OUT_DIM];
__device__ int                 g_cnt[N_NODES];
__device__ int                 g_offs[N_NODES + 1];
__device__ int                 g_cursor[N_NODES];
__device__ int                 g_sorted_cols[N_EDGES];
__device__ unsigned long long  g_state[SCAN_BLK];
// Precomputed B fragments (canonical mma.sync layout, VERIFIED):
// index = ((s*8 + t)*32 + lane), s = kstep (16), t = ntile (8).
__device__ uint2               g_Bfh[4096];
__device__ uint2               g_Bfl[4096];

// ===========================================================================
// Launch 1: histogram + zero lookback state + precompute B fragments.
// ===========================================================================
__global__ __launch_bounds__(256) void hist_kernel(
    const int4* __restrict__ rows4, const float* __restrict__ w)
{
    if (blockIdx.x == 0 && threadIdx.x < SCAN_BLK)
        g_state[threadIdx.x] = 0ULL;

    if (blockIdx.x < 16) {
        const int idx = blockIdx.x * 256 + threadIdx.x;  // (s*8+t)*32 + lane
        const int lane = idx & 31;
        const int st   = idx >> 5;
        const int s    = st >> 3;
        const int t    = st & 7;
        const int n    = t * 8 + (lane >> 2);
        const int k0   = s * 16 + (lane & 3) * 2;

        const float v00 = __ldg(&w[(size_t)k0 * OUT_DIM + n]);
        const float v01 = __ldg(&w[(size_t)(k0 + 1) * OUT_DIM + n]);
        const float v10 = __ldg(&w[(size_t)(k0 + 8) * OUT_DIM + n]);
        const float v11 = __ldg(&w[(size_t)(k0 + 9) * OUT_DIM + n]);

        __nv_bfloat16 h00 = __float2bfloat16(v00);
        __nv_bfloat16 h01 = __float2bfloat16(v01);
        __nv_bfloat16 h10 = __float2bfloat16(v10);
        __nv_bfloat16 h11 = __float2bfloat16(v11);
        __nv_bfloat16 l00 = __float2bfloat16(v00 - __bfloat162float(h00));
        __nv_bfloat16 l01 = __float2bfloat16(v01 - __bfloat162float(h01));
        __nv_bfloat16 l10 = __float2bfloat16(v10 - __bfloat162float(h10));
        __nv_bfloat16 l11 = __float2bfloat16(v11 - __bfloat162float(h11));

        uint2 bh, bl;
        bh.x = (uint32_t)__bfloat16_as_ushort(h00) |
               ((uint32_t)__bfloat16_as_ushort(h01) << 16);
        bh.y = (uint32_t)__bfloat16_as_ushort(h10) |
               ((uint32_t)__bfloat16_as_ushort(h11) << 16);
        bl.x = (uint32_t)__bfloat16_as_ushort(l00) |
               ((uint32_t)__bfloat16_as_ushort(l01) << 16);
        bl.y = (uint32_t)__bfloat16_as_ushort(l10) |
               ((uint32_t)__bfloat16_as_ushort(l11) << 16);
        g_Bfh[idx] = bh;
        g_Bfl[idx] = bl;
    }

    const int i = blockIdx.x * blockDim.x + threadIdx.x;
    if (i < E4) {
        const int4 r = __ldg(&rows4[i]);
        atomicAdd(&g_cnt[r.x], 1);
        atomicAdd(&g_cnt[r.y], 1);
        atomicAdd(&g_cnt[r.z], 1);
        atomicAdd(&g_cnt[r.w], 1);
    }
}

// ===========================================================================
// Launch 2: decoupled-lookback exclusive scan
// ===========================================================================
__global__ __launch_bounds__(256) void scan_kernel()
{
    __shared__ int part[256];
    __shared__ int sbase;
    const int t = threadIdx.x;
    const int b = blockIdx.x;
    const int i0 = b * SCAN_CHUNK + t * 4;

    int c[4];
    int s = 0;
    #pragma unroll
    for (int j = 0; j < 4; j++) {
        c[j] = (i0 + j < N_NODES) ? g_cnt[i0 + j] : 0;
        s += c[j];
    }
    part[t] = s;
    __syncthreads();
    #pragma unroll
    for (int d = 1; d < 256; d <<= 1) {
        int u = (t >= d) ? part[t - d] : 0;
        __syncthreads();
        part[t] += u;
        __syncthreads();
    }
    const int total = part[255];

    if (t == 0) {
        unsigned long long packed =
            ((unsigned long long)total << 2) | (b == 0 ? 2ULL : 1ULL);
        atomicExch(&g_state[b], packed);
        if (b == 0) sbase = 0;
    }
    if (b > 0 && t < 32) {
        int base = 0;
        int p = b - 1;
        while (true) {
            const int i = p - t;
            unsigned long long st;
            if (i >= 0) {
                do { st = atomicAdd(&g_state[i], 0ULL); } while ((st & 3ULL) == 0ULL);
            } else st = 2ULL;
            const int flag = (int)(st & 3ULL);
            const int val  = (int)(st >> 2);
            const unsigned dm = __ballot_sync(0xFFFFFFFFu, flag == 2);
            int contrib;
            if (dm) { const int fd = __ffs(dm) - 1; contrib = (t <= fd) ? val : 0; }
            else contrib = val;
            #pragma unroll
            for (int d = 16; d > 0; d >>= 1)
                contrib += __shfl_down_sync(0xFFFFFFFFu, contrib, d);
            contrib = __shfl_sync(0xFFFFFFFFu, contrib, 0);
            base += contrib;
            if (dm) break;
            p -= 32;
        }
        if (t == 0) {
            sbase = base;
            atomicExch(&g_state[b],
                       ((unsigned long long)(base + total) << 2) | 2ULL);
        }
    }
    __syncthreads();

    int run = sbase + part[t] - s;
    #pragma unroll
    for (int j = 0; j < 4; j++) {
        if (i0 + j < N_NODES) { g_offs[i0 + j] = run; g_cursor[i0 + j] = run; }
        run += c[j];
    }
    if (b == 0 && t == 0) g_offs[N_NODES] = N_EDGES;
}

// ===========================================================================
// Launch 3: bucket fill (8 edges/thread -> MLP 8 on atomic return chain)
// ===========================================================================
__global__ __launch_bounds__(256) void fill_kernel(
    const int4* __restrict__ rows4, const int4* __restrict__ cols4)
{
    const int i = blockIdx.x * blockDim.x + threadIdx.x;
    if (i >= E8) return;
    const int4 r0 = __ldg(&rows4[2 * i]);
    const int4 r1 = __ldg(&rows4[2 * i + 1]);
    const int4 c0 = __ldg(&cols4[2 * i]);
    const int4 c1 = __ldg(&cols4[2 * i + 1]);

    const int p0 = atomicAdd(&g_cursor[r0.x], 1);
    const int p1 = atomicAdd(&g_cursor[r0.y], 1);
    const int p2 = atomicAdd(&g_cursor[r0.z], 1);
    const int p3 = atomicAdd(&g_cursor[r0.w], 1);
    const int p4 = atomicAdd(&g_cursor[r1.x], 1);
    const int p5 = atomicAdd(&g_cursor[r1.y], 1);
    const int p6 = atomicAdd(&g_cursor[r1.z], 1);
    const int p7 = atomicAdd(&g_cursor[r1.w], 1);

    g_sorted_cols[p0] = c0.x;
    g_sorted_cols[p1] = c0.y;
    g_sorted_cols[p2] = c0.z;
    g_sorted_cols[p3] = c0.w;
    g_sorted_cols[p4] = c1.x;
    g_sorted_cols[p5] = c1.y;
    g_sorted_cols[p6] = c1.z;
    g_sorted_cols[p7] = c1.w;
}

// ===========================================================================
// Launch 4 (PROFILED): mma.sync bf16-split GEMM, zero smem, 2 m-tiles/warp
// (R11 shape). A loads use __ldcs (evict-first streaming: A never displaces
// the 64 KB B-fragment table from L1, so B loads stay L1 hits).
// D = Ah*Bh + Ah*Bl + Al*Bh, fp32 accumulation.
// ===========================================================================
__device__ __forceinline__ void cvt_split(float2 v, uint32_t& h, uint32_t& l)
{
    asm("cvt.rn.bf16x2.f32 %0, %1, %2;" : "=r"(h) : "f"(v.y), "f"(v.x));
    const float h0 = __uint_as_float(h << 16);
    const float h1 = __uint_as_float(h & 0xFFFF0000u);
    const float l0 = v.x - h0;
    const float l1 = v.y - h1;
    asm("cvt.rn.bf16x2.f32 %0, %1, %2;" : "=r"(l) : "f"(l1), "f"(l0));
}

__device__ __forceinline__ void mma_bf16(float* d, const uint32_t* a, uint2 b)
{
    asm volatile(
        "mma.sync.aligned.m16n8k16.row.col.f32.bf16.bf16.f32 "
        "{%0,%1,%2,%3}, {%4,%5,%6,%7}, {%8,%9}, {%0,%1,%2,%3};"
        : "+f"(d[0]), "+f"(d[1]), "+f"(d[2]), "+f"(d[3])
        : "r"(a[0]), "r"(a[1]), "r"(a[2]), "r"(a[3]),
          "r"(b.x), "r"(b.y));
}

__global__ __launch_bounds__(128, 4) void gemm_mma_kernel(const float* __restrict__ in)
{
    const int tid  = threadIdx.x;
    const int wid  = tid >> 5;
    const int lane = tid & 31;
    const int m0   = blockIdx.x * 128;

    // Per-mtile row pair (clamped for safe loads; stores are guarded).
    const int rr = m0 + wid * 32 + (lane >> 2);
    int rc[2][2];
    #pragma unroll
    for (int mt = 0; mt < 2; mt++) {
        int ra = rr + mt * 16;
        int rb = ra + 8;
        rc[mt][0] = ra < N_NODES ? ra : (N_NODES - 1);
        rc[mt][1] = rb < N_NODES ? rb : (N_NODES - 1);
    }
    const int kl = (lane & 3) * 2;
    const float* p[2][2];
    #pragma unroll
    for (int mt = 0; mt < 2; mt++) {
        p[mt][0] = in + (size_t)rc[mt][0] * IN_DIM + kl;
        p[mt][1] = in + (size_t)rc[mt][1] * IN_DIM + kl;
    }

    float d[2][8][4];
    #pragma unroll
    for (int mt = 0; mt < 2; mt++)
        #pragma unroll
        for (int t = 0; t < 8; t++)
            #pragma unroll
            for (int j = 0; j < 4; j++) d[mt][t][j] = 0.f;

    #pragma unroll 1
    for (int s = 0; s < 16; s++) {
        const int ko = s * 16;

        // A: 8 independent streaming loads (evict-first, no L1 allocate).
        uint32_t ah[2][4], al[2][4];
        float2 v[2][4];
        #pragma unroll
        for (int mt = 0; mt < 2; mt++) {
            v[mt][0] = __ldcs((const float2*)(p[mt][0] + ko));
            v[mt][1] = __ldcs((const float2*)(p[mt][1] + ko));
            v[mt][2] = __ldcs((const float2*)(p[mt][0] + ko + 8));
            v[mt][3] = __ldcs((const float2*)(p[mt][1] + ko + 8));
        }
        #pragma unroll
        for (int mt = 0; mt < 2; mt++)
            #pragma unroll
            for (int j = 0; j < 4; j++)
                cvt_split(v[mt][j], ah[mt][j], al[mt][j]);

        // B fragments from the L1-resident table; 3-term split accumulate.
        const int bi = (s * 8) * 32 + lane;
        #pragma unroll
        for (int t = 0; t < 8; t++) {
            const uint2 bh = __ldg(&g_Bfh[bi + t * 32]);
            const uint2 bl = __ldg(&g_Bfl[bi + t * 32]);
            #pragma unroll
            for (int mt = 0; mt < 2; mt++) {
                mma_bf16(d[mt][t], ah[mt], bh);
                mma_bf16(d[mt][t], ah[mt], bl);
                mma_bf16(d[mt][t], al[mt], bh);
            }
        }
    }

    // Epilogue: d-frag -> g_X (guarded stores).
    const int rbase = m0 + wid * 32 + (lane >> 2);
    const int cbase = (lane & 3) * 2;
    #pragma unroll
    for (int mt = 0; mt < 2; mt++) {
        #pragma unroll
        for (int t = 0; t < 8; t++) {
            const int c = t * 8 + cbase;
            const int ra = rbase + mt * 16;
            const int rb = ra + 8;
            if (ra < N_NODES)
                *(float2*)(g_X + (size_t)ra * OUT_DIM + c) =
                    make_float2(d[mt][t][0], d[mt][t][1]);
            if (rb < N_NODES)
                *(float2*)(g_X + (size_t)rb * OUT_DIM + c) =
                    make_float2(d[mt][t][2], d[mt][t][3]);
        }
    }
}

// ===========================================================================
// Launch 5: CSR aggregation + fused sigmoid (resets g_cnt for next replay)
// ===========================================================================
__global__ __launch_bounds__(256) void aggregate_kernel(float* __restrict__ out)
{
    const int hw   = threadIdx.x >> 4;
    const int hl   = threadIdx.x & 15;
    const int node = blockIdx.x * 16 + hw;
    if (node >= N_NODES) return;

    const int start = g_offs[node];
    const int end   = g_offs[node + 1];
    if (hl == 0) g_cnt[node] = 0;

    const float* Xl = g_X + hl * 4;

    float4 A = make_float4(0.f, 0.f, 0.f, 0.f);
    float4 B = make_float4(0.f, 0.f, 0.f, 0.f);

    int idx = start;
    for (; idx + 8 <= end; idx += 8) {
        int c[8];
        #pragma unroll
        for (int j = 0; j < 8; j++) c[j] = __ldg(&g_sorted_cols[idx + j]);
        float4 v[8];
        #pragma unroll
        for (int j = 0; j < 8; j++)
            v[j] = __ldg((const float4*)(Xl + (size_t)c[j] * OUT_DIM));
        #pragma unroll
        for (int j = 0; j < 8; j += 2) {
            A.x += v[j].x;     A.y += v[j].y;
            A.z += v[j].z;     A.w += v[j].w;
            B.x += v[j + 1].x; B.y += v[j + 1].y;
            B.z += v[j + 1].z; B.w += v[j + 1].w;
        }
    }
    for (; idx + 2 <= end; idx += 2) {
        const int c0 = __ldg(&g_sorted_cols[idx]);
        const int c1 = __ldg(&g_sorted_cols[idx + 1]);
        const float4 v0 = __ldg((const float4*)(Xl + (size_t)c0 * OUT_DIM));
        const float4 v1 = __ldg((const float4*)(Xl + (size_t)c1 * OUT_DIM));
        A.x += v0.x; A.y += v0.y; A.z += v0.z; A.w += v0.w;
        B.x += v1.x; B.y += v1.y; B.z += v1.z; B.w += v1.w;
    }
    if (idx < end) {
        const int c = __ldg(&g_sorted_cols[idx]);
        const float4 v = __ldg((const float4*)(Xl + (size_t)c * OUT_DIM));
        A.x += v.x; A.y += v.y; A.z += v.z; A.w += v.w;
    }
    A.x += B.x; A.y += B.y; A.z += B.z; A.w += B.w;

    float4 o;
    o.x = 1.0f / (1.0f + __expf(-A.x));
    o.y = 1.0f / (1.0f + __expf(-A.y));
    o.z = 1.0f / (1.0f + __expf(-A.z));
    o.w = 1.0f / (1.0f + __expf(-A.w));
    *(float4*)(out + (size_t)node * OUT_DIM + hl * 4) = o;
}

extern "C" void kernel_launch(void* const* d_in, const int* in_sizes, int n_in,
                              void* d_out, int out_size)
{
    const float* inputs = (const float*)d_in[0];
    const int*   eidx   = (const int*)d_in[1];
    const float* weight = (const float*)d_in[2];
    float*       out    = (float*)d_out;

    const int4* erows4 = (const int4*)eidx;
    const int4* ecols4 = (const int4*)(eidx + N_EDGES);

    hist_kernel<<<(E4 + 255) / 256, 256>>>(erows4, weight);         // 1
    scan_kernel<<<SCAN_BLK, 256>>>();                               // 2
    fill_kernel<<<(E8 + 255) / 256, 256>>>(erows4, ecols4);         // 3
    gemm_mma_kernel<<<TC_BLOCKS, 128>>>(inputs);                    // 4 (profiled)
    aggregate_kernel<<<(N_NODES + 15) / 16, 256>>>(out);            // 5
}